// round 1
// baseline (speedup 1.0000x reference)
#include <cuda_runtime.h>
#include <math.h>

#define Bz   32
#define Nn   1024
#define CIN  128
#define Ff   64
#define OUTD 10
#define MAXDEG 192
#define EPSf 1e-5f

// ---------------- scratch (device globals; no allocation) ----------------
__device__ int   g_adj[Bz * Nn * MAXDEG];   // fixed-width adjacency lists (~25 MB)
__device__ int   g_deg[Bz * Nn];
__device__ float g_x[Bz * Nn * Ff];         // current node features
__device__ float g_u[Bz * Nn * Ff];         // x @ W
__device__ float g_D[Bz * Nn];              // (rowsum+eps)^-0.5
__device__ float g_Dm[Bz * Nn];             // D * mask (neighbor weight)
__device__ float g_mask[Bz * Nn];
__device__ int   g_nnodes[Bz];
__device__ float g_y[Bz * Nn];              // pooling scores

// ---------------- 1) adjacency extraction: one pass over A ----------------
// one warp per (b,i) row; ballot-compact nonzero column indices
__global__ void build_adj(const float* __restrict__ A,
                          const float* __restrict__ mask,
                          const int*   __restrict__ nn) {
    int warp = (blockIdx.x * blockDim.x + threadIdx.x) >> 5;
    int lane = threadIdx.x & 31;
    if (blockIdx.x == 0 && threadIdx.x < Bz) g_nnodes[threadIdx.x] = nn[threadIdx.x];
    if (warp >= Bz * Nn) return;
    const float* row = A + (size_t)warp * Nn;
    int* out = g_adj + (size_t)warp * MAXDEG;
    int cnt = 0;
    #pragma unroll 4
    for (int it = 0; it < Nn / 32; ++it) {
        int j = it * 32 + lane;
        float v = row[j];
        unsigned bal = __ballot_sync(0xffffffffu, v != 0.0f);
        if (v != 0.0f) {
            int pos = cnt + __popc(bal & ((1u << lane) - 1u));
            if (pos < MAXDEG) out[pos] = j;
        }
        cnt += __popc(bal);
    }
    if (lane == 0) {
        g_deg[warp]  = min(cnt, MAXDEG);
        g_mask[warp] = mask[warp];
    }
}

// ---------------- 2) u = X @ W  (per-warp row GEMM, W in shared) ----------
template <int K, bool FROMG>
__global__ void gemm_xw(const float* __restrict__ Xext,
                        const float* __restrict__ W) {
    __shared__ float Ws[K * Ff];
    __shared__ float Xs[8][K];
    const float* X = FROMG ? (const float*)g_x : Xext;
    for (int i = threadIdx.x; i < K * Ff; i += blockDim.x) Ws[i] = W[i];
    int wid = threadIdx.x >> 5, lane = threadIdx.x & 31;
    int row = blockIdx.x * 8 + wid;
    __syncthreads();
    const float* xr = X + (size_t)row * K;
    #pragma unroll
    for (int k = lane; k < K; k += 32) Xs[wid][k] = xr[k];
    __syncwarp();
    float a0 = 0.f, a1 = 0.f;
    #pragma unroll 8
    for (int k = 0; k < K; ++k) {
        float xv = Xs[wid][k];
        a0 = fmaf(xv, Ws[k * Ff + lane],      a0);
        a1 = fmaf(xv, Ws[k * Ff + lane + 32], a1);
    }
    float* ur = g_u + (size_t)row * Ff;
    ur[lane] = a0; ur[lane + 32] = a1;
}

// ---------------- 3) degree under current mask -> D, D*m ------------------
__global__ void compute_D() {
    int node = (blockIdx.x * blockDim.x + threadIdx.x) >> 5;
    int lane = threadIdx.x & 31;
    if (node >= Bz * Nn) return;
    int base = node & ~(Nn - 1);
    float m = g_mask[node];
    int deg = g_deg[node];
    const int* adj = g_adj + (size_t)node * MAXDEG;
    float cnt = 0.f;
    for (int t = lane; t < deg; t += 32) cnt += g_mask[base + adj[t]];
    #pragma unroll
    for (int o = 16; o; o >>= 1) cnt += __shfl_xor_sync(0xffffffffu, cnt, o);
    if (lane == 0) {
        float rowsum = m * cnt + 1.0f;        // +1 from identity (A_hat = A + I)
        float D = 1.0f / sqrtf(rowsum + EPSf);
        g_D[node]  = D;
        g_Dm[node] = D * m;
    }
}

// ---------------- 4) h = relu(D*(sum_j w_j*u_j + D*u_i) + b) --------------
// one warp per node, 2 features per lane; gathers served from L2 (u = 8MB)
__global__ void spmm_relu(const float* __restrict__ bias) {
    int node = (blockIdx.x * blockDim.x + threadIdx.x) >> 5;
    int lane = threadIdx.x & 31;
    if (node >= Bz * Nn) return;
    int base = node & ~(Nn - 1);
    float Di = g_D[node];
    const float* ui = g_u + (size_t)node * Ff;
    float a0 = Di * ui[lane];
    float a1 = Di * ui[lane + 32];
    if (g_mask[node] > 0.f) {                 // masked rows keep only the diag term
        int deg = g_deg[node];
        const int* adj = g_adj + (size_t)node * MAXDEG;
        float s0 = 0.f, s1 = 0.f;
        for (int t = 0; t < deg; ++t) {
            int j = base + adj[t];
            float w = g_Dm[j];
            const float* uj = g_u + (size_t)j * Ff;
            s0 = fmaf(w, uj[lane],      s0);
            s1 = fmaf(w, uj[lane + 32], s1);
        }
        a0 += s0; a1 += s1;
    }
    float* xo = g_x + (size_t)node * Ff;
    xo[lane]      = fmaxf(fmaf(Di, a0, bias[lane]),      0.f);
    xo[lane + 32] = fmaxf(fmaf(Di, a1, bias[lane + 32]), 0.f);
}

// ---------------- 5a) y = (x . p) / ||p|| ---------------------------------
__global__ void pool_score(const float* __restrict__ p) {
    int node = (blockIdx.x * blockDim.x + threadIdx.x) >> 5;
    int lane = threadIdx.x & 31;
    if (node >= Bz * Nn) return;
    const float* xi = g_x + (size_t)node * Ff;
    float p0 = p[lane], p1 = p[lane + 32];
    float d = xi[lane] * p0 + xi[lane + 32] * p1;
    float n = p0 * p0 + p1 * p1;
    #pragma unroll
    for (int o = 16; o; o >>= 1) {
        d += __shfl_xor_sync(0xffffffffu, d, o);
        n += __shfl_xor_sync(0xffffffffu, n, o);
    }
    if (lane == 0) g_y[node] = d / sqrtf(n);
}

// ---------------- 5b) ranks + drop + rescale (one block per graph) --------
__global__ void pool_apply() {
    __shared__ float ys[Nn];
    __shared__ float sc[Nn];
    __shared__ int   s_nrem;
    int b = blockIdx.x, i = threadIdx.x;
    int node = b * Nn + i;
    float m = g_mask[node];
    float y = g_y[node];
    float ye = (m > 0.f) ? y : INFINITY;      // invalid nodes rank last (stable)
    ys[i] = ye;
    if (i == 0) {
        int n  = g_nnodes[b];
        int nr = (int)((float)n * 0.2f);      // bit-matches f32(1.0-0.8) * f32(n)
        s_nrem = nr;
        g_nnodes[b] = n - nr;
    }
    __syncthreads();
    int rank = 0;
    #pragma unroll 8
    for (int j = 0; j < Nn; ++j) {
        float yj = ys[j];
        rank += (yj < ye) || ((yj == ye) && (j < i));   // stable argsort rank
    }
    float newm = (m > 0.f && rank >= s_nrem) ? 1.f : 0.f;
    g_mask[node] = newm;
    sc[i] = tanhf(y) * newm;
    __syncthreads();
    float* xb = g_x + (size_t)b * Nn * Ff;    // coalesced rescale of x
    for (int idx = i; idx < Nn * Ff; idx += Nn) xb[idx] *= sc[idx >> 6];
}

// ---------------- 6) global max over nodes + final FC ---------------------
__global__ void final_fc(const float* __restrict__ Wfc,
                         const float* __restrict__ bfc,
                         float* __restrict__ out) {
    __shared__ float pm[8][Ff];
    __shared__ float gm[Ff];
    int b = blockIdx.x;
    int f = threadIdx.x & 63;
    int c = threadIdx.x >> 6;                 // 512 threads -> 8 node-chunks
    const float* xb = g_x + (size_t)b * Nn * Ff;
    float mx = -INFINITY;
    for (int node = c; node < Nn; node += 8)
        mx = fmaxf(mx, xb[node * Ff + f]);
    pm[c][f] = mx;
    __syncthreads();
    if (threadIdx.x < Ff) {
        float v = pm[0][f];
        #pragma unroll
        for (int k = 1; k < 8; ++k) v = fmaxf(v, pm[k][f]);
        gm[f] = v;
    }
    __syncthreads();
    if (threadIdx.x < OUTD) {
        float acc = bfc[threadIdx.x];
        #pragma unroll
        for (int ff = 0; ff < Ff; ++ff)
            acc = fmaf(gm[ff], Wfc[ff * OUTD + threadIdx.x], acc);
        out[b * OUTD + threadIdx.x] = acc;
    }
}

// ---------------- launch ---------------------------------------------------
extern "C" void kernel_launch(void* const* d_in, const int* in_sizes, int n_in,
                              void* d_out, int out_size) {
    const float* x    = (const float*)d_in[0];
    const float* A    = (const float*)d_in[1];
    const float* mask = (const float*)d_in[2];
    const int*   nn   = (const int*)  d_in[3];
    const float* W0   = (const float*)d_in[4];
    const float* b0   = (const float*)d_in[5];
    const float* W1   = (const float*)d_in[6];
    const float* b1   = (const float*)d_in[7];
    const float* W2   = (const float*)d_in[8];
    const float* b2   = (const float*)d_in[9];
    const float* p0   = (const float*)d_in[10];
    const float* p1   = (const float*)d_in[11];
    const float* Wfc  = (const float*)d_in[12];
    const float* bfc  = (const float*)d_in[13];
    float* out = (float*)d_out;

    const int WGRID = (Bz * Nn) / 8;   // 8 warps per 256-thread block

    build_adj<<<WGRID, 256>>>(A, mask, nn);

    // layer 0
    gemm_xw<CIN, false><<<WGRID, 256>>>(x, W0);
    compute_D<<<WGRID, 256>>>();
    spmm_relu<<<WGRID, 256>>>(b0);
    pool_score<<<WGRID, 256>>>(p0);
    pool_apply<<<Bz, Nn>>>();

    // layer 1
    gemm_xw<Ff, true><<<WGRID, 256>>>(nullptr, W1);
    compute_D<<<WGRID, 256>>>();
    spmm_relu<<<WGRID, 256>>>(b1);
    pool_score<<<WGRID, 256>>>(p1);
    pool_apply<<<Bz, Nn>>>();

    // layer 2
    gemm_xw<Ff, true><<<WGRID, 256>>>(nullptr, W2);
    compute_D<<<WGRID, 256>>>();
    spmm_relu<<<WGRID, 256>>>(b2);

    final_fc<<<Bz, 512>>>(Wfc, bfc, out);
}

// round 2
// speedup vs baseline: 1.1719x; 1.1719x over previous
#include <cuda_runtime.h>
#include <math.h>

#define Bz   32
#define Nn   1024
#define CIN  128
#define Ff   64
#define OUTD 10
#define MAXDEG 192
#define EPSf 1e-5f

// ---------------- scratch (device globals; no allocation) ----------------
__device__ int   g_adj[Bz * Nn * MAXDEG];   // fixed-width adjacency lists
__device__ int   g_deg[Bz * Nn];
__device__ float g_x[Bz * Nn * Ff];         // gconv output (never rescaled)
__device__ float g_u[Bz * Nn * Ff];         // sc * (x @ W)
__device__ float g_D[Bz * Nn];              // (rowsum+eps)^-0.5
__device__ float g_Dm[Bz * Nn];             // D * mask (neighbor weight)
__device__ float g_mask[Bz * Nn];
__device__ float g_sc[Bz * Nn];             // tanh(y) * new_mask, applied in next gemm
__device__ int   g_nnodes[Bz * 3];          // per-pool-generation node counts
__device__ float g_y[Bz * Nn];              // pooling scores

// ---------------- 1) adjacency extraction: one pass over A ----------------
__global__ void build_adj(const float* __restrict__ A,
                          const float* __restrict__ mask,
                          const int*   __restrict__ nn) {
    int warp = (blockIdx.x * blockDim.x + threadIdx.x) >> 5;
    int lane = threadIdx.x & 31;
    if (blockIdx.x == 0 && threadIdx.x < Bz) g_nnodes[threadIdx.x] = nn[threadIdx.x];
    if (warp >= Bz * Nn) return;
    const float* row = A + (size_t)warp * Nn;
    int* out = g_adj + (size_t)warp * MAXDEG;
    int cnt = 0;
    #pragma unroll 4
    for (int it = 0; it < Nn / 32; ++it) {
        int j = it * 32 + lane;
        float v = row[j];
        unsigned bal = __ballot_sync(0xffffffffu, v != 0.0f);
        if (v != 0.0f) {
            int pos = cnt + __popc(bal & ((1u << lane) - 1u));
            if (pos < MAXDEG) out[pos] = j;
        }
        cnt += __popc(bal);
    }
    if (lane == 0) {
        g_deg[warp]  = min(cnt, MAXDEG);
        g_mask[warp] = mask[warp];
    }
}

// ---------------- 2) u = sc * (X @ W)  (per-warp row GEMM) ----------------
template <int K, bool FROMG, bool SC>
__global__ void gemm_xw(const float* __restrict__ Xext,
                        const float* __restrict__ W) {
    __shared__ float Ws[K * Ff];
    __shared__ float Xs[8][K];
    const float* X = FROMG ? (const float*)g_x : Xext;
    for (int i = threadIdx.x; i < K * Ff; i += blockDim.x) Ws[i] = W[i];
    int wid = threadIdx.x >> 5, lane = threadIdx.x & 31;
    int row = blockIdx.x * 8 + wid;
    __syncthreads();
    const float* xr = X + (size_t)row * K;
    #pragma unroll
    for (int k = lane; k < K; k += 32) Xs[wid][k] = xr[k];
    __syncwarp();
    float a0 = 0.f, a1 = 0.f;
    #pragma unroll 8
    for (int k = 0; k < K; ++k) {
        float xv = Xs[wid][k];
        a0 = fmaf(xv, Ws[k * Ff + lane],      a0);
        a1 = fmaf(xv, Ws[k * Ff + lane + 32], a1);
    }
    if (SC) {                                 // pooling rescale folded in:
        float s = g_sc[row];                  // (sc*x)@W == sc*(x@W)
        a0 *= s; a1 *= s;
    }
    float* ur = g_u + (size_t)row * Ff;
    ur[lane] = a0; ur[lane + 32] = a1;
}

// ---------------- 3) degree under current mask -> D, D*m ------------------
__global__ void compute_D() {
    int node = (blockIdx.x * blockDim.x + threadIdx.x) >> 5;
    int lane = threadIdx.x & 31;
    if (node >= Bz * Nn) return;
    int base = node & ~(Nn - 1);
    float m = g_mask[node];
    int deg = g_deg[node];
    const int* adj = g_adj + (size_t)node * MAXDEG;
    float cnt = 0.f;
    for (int t = lane; t < deg; t += 32) cnt += g_mask[base + adj[t]];
    #pragma unroll
    for (int o = 16; o; o >>= 1) cnt += __shfl_xor_sync(0xffffffffu, cnt, o);
    if (lane == 0) {
        float rowsum = m * cnt + 1.0f;        // +1 from identity (A_hat = A + I)
        float D = 1.0f / sqrtf(rowsum + EPSf);
        g_D[node]  = D;
        g_Dm[node] = D * m;
    }
}

// ---------------- 4) h = relu(D*(sum_j w_j*u_j + D*u_i) + b) --------------
// chunked gather: 32 lanes load 32 (index, weight) pairs in parallel, then
// a fixed-trip 32-iteration shfl-broadcast loop of independent u loads.
template <bool POOL>
__global__ void spmm_relu(const float* __restrict__ bias,
                          const float* __restrict__ p) {
    int node = (blockIdx.x * blockDim.x + threadIdx.x) >> 5;
    int lane = threadIdx.x & 31;
    if (node >= Bz * Nn) return;
    int base = node & ~(Nn - 1);
    float Di = g_D[node];
    const float* ui = g_u + (size_t)node * Ff;
    float a0 = Di * ui[lane];
    float a1 = Di * ui[lane + 32];
    if (g_mask[node] > 0.f) {
        int deg = g_deg[node];
        const int* adj = g_adj + (size_t)node * MAXDEG;
        float s0 = 0.f, s1 = 0.f;
        for (int c = 0; c < deg; c += 32) {
            int idx  = c + lane;
            int myj  = base + ((idx < deg) ? adj[idx] : 0);   // coalesced
            float myw = (idx < deg) ? g_Dm[myj] : 0.f;        // 32-wide gather
            #pragma unroll
            for (int k = 0; k < 32; ++k) {
                int   j = __shfl_sync(0xffffffffu, myj, k);
                float w = __shfl_sync(0xffffffffu, myw, k);
                const float* uj = g_u + (size_t)j * Ff;
                s0 = fmaf(w, uj[lane],      s0);
                s1 = fmaf(w, uj[lane + 32], s1);
            }
        }
        a0 += s0; a1 += s1;
    }
    float x0 = fmaxf(fmaf(Di, a0, bias[lane]),      0.f);
    float x1 = fmaxf(fmaf(Di, a1, bias[lane + 32]), 0.f);
    float* xo = g_x + (size_t)node * Ff;
    xo[lane]      = x0;
    xo[lane + 32] = x1;
    if (POOL) {                               // fused pooling score
        float p0 = p[lane], p1 = p[lane + 32];
        float d = x0 * p0 + x1 * p1;
        float n = p0 * p0 + p1 * p1;
        #pragma unroll
        for (int o = 16; o; o >>= 1) {
            d += __shfl_xor_sync(0xffffffffu, d, o);
            n += __shfl_xor_sync(0xffffffffu, n, o);
        }
        if (lane == 0) g_y[node] = d / sqrtf(n);
    }
}

// ---------------- 5) ranks + drop -> sc, mask (4 blocks per graph) --------
__global__ void pool_apply(int step) {
    __shared__ float ys[Nn];
    int b = blockIdx.x >> 2;
    int i = (blockIdx.x & 3) * 256 + threadIdx.x;
    int node = b * Nn + i;
    for (int j = threadIdx.x; j < Nn; j += 256) {
        float mj = g_mask[b * Nn + j];
        ys[j] = (mj > 0.f) ? g_y[b * Nn + j] : INFINITY;
    }
    if ((blockIdx.x & 3) == 0 && threadIdx.x == 0) {
        int n  = g_nnodes[step * Bz + b];
        int nr = (int)((float)n * 0.2f);      // bit-matches f32 arithmetic
        g_nnodes[(step + 1) * Bz + b] = n - nr;
    }
    __syncthreads();
    float m  = g_mask[node];
    float y  = g_y[node];
    float ye = ys[i];
    int rank = 0;                             // stable argsort rank, split loops
    #pragma unroll 8
    for (int j = 0; j < Nn; ++j) {
        float yj = ys[j];
        rank += (j < i) ? (yj <= ye) : (yj < ye);
    }
    int n  = g_nnodes[step * Bz + b];
    int nr = (int)((float)n * 0.2f);
    float newm = (m > 0.f && rank >= nr) ? 1.f : 0.f;
    g_mask[node] = newm;
    g_sc[node]   = tanhf(y) * newm;           // consumed by next gemm
}

// ---------------- 6) global max over nodes + final FC ---------------------
__global__ void final_fc(const float* __restrict__ Wfc,
                         const float* __restrict__ bfc,
                         float* __restrict__ out) {
    __shared__ float pm[8][Ff];
    __shared__ float gm[Ff];
    int b = blockIdx.x;
    int f = threadIdx.x & 63;
    int c = threadIdx.x >> 6;
    const float* xb = g_x + (size_t)b * Nn * Ff;
    float mx = -INFINITY;
    for (int node = c; node < Nn; node += 8)
        mx = fmaxf(mx, xb[node * Ff + f]);
    pm[c][f] = mx;
    __syncthreads();
    if (threadIdx.x < Ff) {
        float v = pm[0][f];
        #pragma unroll
        for (int k = 1; k < 8; ++k) v = fmaxf(v, pm[k][f]);
        gm[f] = v;
    }
    __syncthreads();
    if (threadIdx.x < OUTD) {
        float acc = bfc[threadIdx.x];
        #pragma unroll
        for (int ff = 0; ff < Ff; ++ff)
            acc = fmaf(gm[ff], Wfc[ff * OUTD + threadIdx.x], acc);
        out[b * OUTD + threadIdx.x] = acc;
    }
}

// ---------------- launch ---------------------------------------------------
extern "C" void kernel_launch(void* const* d_in, const int* in_sizes, int n_in,
                              void* d_out, int out_size) {
    const float* x    = (const float*)d_in[0];
    const float* A    = (const float*)d_in[1];
    const float* mask = (const float*)d_in[2];
    const int*   nn   = (const int*)  d_in[3];
    const float* W0   = (const float*)d_in[4];
    const float* b0   = (const float*)d_in[5];
    const float* W1   = (const float*)d_in[6];
    const float* b1   = (const float*)d_in[7];
    const float* W2   = (const float*)d_in[8];
    const float* b2   = (const float*)d_in[9];
    const float* p0   = (const float*)d_in[10];
    const float* p1   = (const float*)d_in[11];
    const float* Wfc  = (const float*)d_in[12];
    const float* bfc  = (const float*)d_in[13];
    float* out = (float*)d_out;

    const int WGRID = (Bz * Nn) / 8;   // 8 warps per 256-thread block

    build_adj<<<WGRID, 256>>>(A, mask, nn);

    // layer 0
    gemm_xw<CIN, false, false><<<WGRID, 256>>>(x, W0);
    compute_D<<<WGRID, 256>>>();
    spmm_relu<true><<<WGRID, 256>>>(b0, p0);
    pool_apply<<<Bz * 4, 256>>>(0);

    // layer 1
    gemm_xw<Ff, true, true><<<WGRID, 256>>>(nullptr, W1);
    compute_D<<<WGRID, 256>>>();
    spmm_relu<true><<<WGRID, 256>>>(b1, p1);
    pool_apply<<<Bz * 4, 256>>>(1);

    // layer 2
    gemm_xw<Ff, true, true><<<WGRID, 256>>>(nullptr, W2);
    compute_D<<<WGRID, 256>>>();
    spmm_relu<false><<<WGRID, 256>>>(b2, nullptr);

    final_fc<<<Bz, 512>>>(Wfc, bfc, out);
}

// round 3
// speedup vs baseline: 1.2762x; 1.0890x over previous
#include <cuda_runtime.h>
#include <math.h>

#define Bz   32
#define Nn   1024
#define CIN  128
#define Ff   64
#define OUTD 10
#define MAXDEG 192
#define EPSf 1e-5f

// ---------------- scratch (device globals; no allocation) ----------------
__device__ int   g_adj[Bz * Nn * MAXDEG];   // adjacency lists (compacted per layer)
__device__ int   g_deg[Bz * Nn];
__device__ float g_x[Bz * Nn * Ff];         // gconv output
__device__ float g_uw[Bz * Nn * Ff];        // D*m*u  (gathered by spmm)
__device__ float g_ud[Bz * Nn * Ff];        // D*D*u  (diag term)
__device__ float g_D[Bz * Nn];
__device__ float g_mask[Bz * Nn];
__device__ float g_sc[Bz * Nn];             // tanh(y)*new_mask (folded into next gemm)
__device__ int   g_nnodes[Bz * 3];
__device__ float g_y[Bz * Nn];

// ---------------- 1) adjacency extraction: one pass over A ----------------
__global__ void build_adj(const float* __restrict__ A,
                          const float* __restrict__ mask,
                          const int*   __restrict__ nn) {
    int warp = (blockIdx.x * blockDim.x + threadIdx.x) >> 5;
    int lane = threadIdx.x & 31;
    if (blockIdx.x == 0 && threadIdx.x < Bz) g_nnodes[threadIdx.x] = nn[threadIdx.x];
    if (warp >= Bz * Nn) return;
    const float* row = A + (size_t)warp * Nn;
    int* out = g_adj + (size_t)warp * MAXDEG;
    int cnt = 0;
    #pragma unroll 4
    for (int it = 0; it < Nn / 32; ++it) {
        int j = it * 32 + lane;
        float v = row[j];
        unsigned bal = __ballot_sync(0xffffffffu, v != 0.0f);
        if (v != 0.0f) {
            int pos = cnt + __popc(bal & ((1u << lane) - 1u));
            if (pos < MAXDEG) out[pos] = j;
        }
        cnt += __popc(bal);
    }
    if (lane == 0) {
        g_deg[warp]  = min(cnt, MAXDEG);
        g_mask[warp] = mask[warp];
    }
}

// ------- 2) fused: u = sc*(X@W); D/degree; adj compaction; uw/ud ---------
// one warp per row; lane owns output features (2*lane, 2*lane+1)
template <int K, bool FROMG, bool SC>
__global__ void gemm_fused(const float* __restrict__ Xext,
                           const float* __restrict__ W) {
    __shared__ float2 Ws[K * 32];
    __shared__ float  Xs[8][K];
    const float* X = FROMG ? (const float*)g_x : Xext;
    const float2* W2 = (const float2*)W;
    for (int i = threadIdx.x; i < K * 32; i += blockDim.x) Ws[i] = W2[i];
    int wid = threadIdx.x >> 5, lane = threadIdx.x & 31;
    int row = blockIdx.x * 8 + wid;
    __syncthreads();
    const float* xr = X + (size_t)row * K;
    #pragma unroll
    for (int k = lane; k < K; k += 32) Xs[wid][k] = xr[k];
    __syncwarp();
    float a0 = 0.f, a1 = 0.f;
    #pragma unroll 8
    for (int k = 0; k < K; ++k) {
        float xv = Xs[wid][k];
        float2 wv = Ws[k * 32 + lane];
        a0 = fmaf(xv, wv.x, a0);
        a1 = fmaf(xv, wv.y, a1);
    }
    if (SC) {                                 // pooling rescale: (sc*x)@W == sc*(x@W)
        float s = g_sc[row];
        a0 *= s; a1 *= s;
    }
    // --- fused degree count + in-place adjacency compaction under mask ---
    int base = row & ~(Nn - 1);
    float m  = g_mask[row];
    int  deg = g_deg[row];
    int* adj = g_adj + (size_t)row * MAXDEG;
    int wcnt = 0;
    for (int c = 0; c < deg; c += 32) {
        int idx = c + lane;
        int j = (idx < deg) ? adj[idx] : 0;
        bool act = (idx < deg) && (g_mask[base + j] > 0.f);
        unsigned bal = __ballot_sync(0xffffffffu, act);
        if (act) adj[wcnt + __popc(bal & ((1u << lane) - 1u))] = j;
        wcnt += __popc(bal);
    }
    float rowsum = m * (float)wcnt + 1.0f;    // +1: identity in A_hat
    float D = 1.0f / sqrtf(rowsum + EPSf);
    if (lane == 0) { g_deg[row] = wcnt; g_D[row] = D; }
    float Dm = D * m, DD = D * D;
    ((float2*)g_uw)[(size_t)row * 32 + lane] = make_float2(Dm * a0, Dm * a1);
    ((float2*)g_ud)[(size_t)row * 32 + lane] = make_float2(DD * a0, DD * a1);
}

// -------- 3) x = relu(D*sum_adj(uw_j) + ud_i + b)  [+ pooling score] ------
template <bool POOL>
__global__ void spmm_relu(const float* __restrict__ bias,
                          const float* __restrict__ p) {
    int node = (blockIdx.x * blockDim.x + threadIdx.x) >> 5;
    int lane = threadIdx.x & 31;
    if (node >= Bz * Nn) return;
    int base = node & ~(Nn - 1);
    float D = g_D[node];
    float2 ud = ((const float2*)g_ud)[(size_t)node * 32 + lane];
    float2 bv = ((const float2*)bias)[lane];
    float s0 = 0.f, s1 = 0.f;
    if (g_mask[node] > 0.f) {
        const int* adj = g_adj + (size_t)node * MAXDEG;
        int deg = g_deg[node];
        const float2* uwb = (const float2*)g_uw + (size_t)base * 32 + lane;
        int t = 0;
        for (; t + 4 <= deg; t += 4) {         // uniform int4 index load,
            int4 jv = *(const int4*)(adj + t); // 4 independent 64b gathers
            float2 v0 = uwb[jv.x * 32];
            float2 v1 = uwb[jv.y * 32];
            float2 v2 = uwb[jv.z * 32];
            float2 v3 = uwb[jv.w * 32];
            s0 += (v0.x + v1.x) + (v2.x + v3.x);
            s1 += (v0.y + v1.y) + (v2.y + v3.y);
        }
        for (; t < deg; ++t) {
            float2 v = uwb[adj[t] * 32];
            s0 += v.x; s1 += v.y;
        }
    }
    float x0 = fmaxf(fmaf(D, s0, ud.x + bv.x), 0.f);
    float x1 = fmaxf(fmaf(D, s1, ud.y + bv.y), 0.f);
    ((float2*)g_x)[(size_t)node * 32 + lane] = make_float2(x0, x1);
    if (POOL) {
        float2 pv = ((const float2*)p)[lane];
        float d = x0 * pv.x + x1 * pv.y;
        float n = pv.x * pv.x + pv.y * pv.y;
        #pragma unroll
        for (int o = 16; o; o >>= 1) {
            d += __shfl_xor_sync(0xffffffffu, d, o);
            n += __shfl_xor_sync(0xffffffffu, n, o);
        }
        if (lane == 0) g_y[node] = d / sqrtf(n);
    }
}

// ---------------- 4) ranks + drop -> sc, mask (4 blocks per graph) --------
__global__ void pool_apply(int step) {
    __shared__ float ys[Nn];
    int b = blockIdx.x >> 2;
    int i = (blockIdx.x & 3) * 256 + threadIdx.x;
    int node = b * Nn + i;
    for (int j = threadIdx.x; j < Nn; j += 256) {
        float mj = g_mask[b * Nn + j];
        ys[j] = (mj > 0.f) ? g_y[b * Nn + j] : INFINITY;
    }
    if ((blockIdx.x & 3) == 0 && threadIdx.x == 0) {
        int n  = g_nnodes[step * Bz + b];
        int nr = (int)((float)n * 0.2f);      // bit-matches f32 arithmetic
        g_nnodes[(step + 1) * Bz + b] = n - nr;
    }
    __syncthreads();
    float m  = g_mask[node];
    float y  = g_y[node];
    float ye = ys[i];
    int rank = 0;                             // stable argsort rank
    #pragma unroll 8
    for (int j = 0; j < Nn; ++j) {
        float yj = ys[j];
        rank += (j < i) ? (yj <= ye) : (yj < ye);
    }
    int n  = g_nnodes[step * Bz + b];
    int nr = (int)((float)n * 0.2f);
    float newm = (m > 0.f && rank >= nr) ? 1.f : 0.f;
    g_mask[node] = newm;
    g_sc[node]   = tanhf(y) * newm;
}

// ---------------- 5) global max over nodes + final FC ---------------------
__global__ void final_fc(const float* __restrict__ Wfc,
                         const float* __restrict__ bfc,
                         float* __restrict__ out) {
    __shared__ float pm[8][Ff];
    __shared__ float gm[Ff];
    int b = blockIdx.x;
    int f = threadIdx.x & 63;
    int c = threadIdx.x >> 6;
    const float* xb = g_x + (size_t)b * Nn * Ff;
    float mx = -INFINITY;
    for (int node = c; node < Nn; node += 8)
        mx = fmaxf(mx, xb[node * Ff + f]);
    pm[c][f] = mx;
    __syncthreads();
    if (threadIdx.x < Ff) {
        float v = pm[0][f];
        #pragma unroll
        for (int k = 1; k < 8; ++k) v = fmaxf(v, pm[k][f]);
        gm[f] = v;
    }
    __syncthreads();
    if (threadIdx.x < OUTD) {
        float acc = bfc[threadIdx.x];
        #pragma unroll
        for (int ff = 0; ff < Ff; ++ff)
            acc = fmaf(gm[ff], Wfc[ff * OUTD + threadIdx.x], acc);
        out[b * OUTD + threadIdx.x] = acc;
    }
}

// ---------------- launch ---------------------------------------------------
extern "C" void kernel_launch(void* const* d_in, const int* in_sizes, int n_in,
                              void* d_out, int out_size) {
    const float* x    = (const float*)d_in[0];
    const float* A    = (const float*)d_in[1];
    const float* mask = (const float*)d_in[2];
    const int*   nn   = (const int*)  d_in[3];
    const float* W0   = (const float*)d_in[4];
    const float* b0   = (const float*)d_in[5];
    const float* W1   = (const float*)d_in[6];
    const float* b1   = (const float*)d_in[7];
    const float* W2   = (const float*)d_in[8];
    const float* b2   = (const float*)d_in[9];
    const float* p0   = (const float*)d_in[10];
    const float* p1   = (const float*)d_in[11];
    const float* Wfc  = (const float*)d_in[12];
    const float* bfc  = (const float*)d_in[13];
    float* out = (float*)d_out;

    const int WGRID = (Bz * Nn) / 8;   // 8 warps per 256-thread block

    build_adj<<<WGRID, 256>>>(A, mask, nn);

    // layer 0
    gemm_fused<CIN, false, false><<<WGRID, 256>>>(x, W0);
    spmm_relu<true><<<WGRID, 256>>>(b0, p0);
    pool_apply<<<Bz * 4, 256>>>(0);

    // layer 1
    gemm_fused<Ff, true, true><<<WGRID, 256>>>(nullptr, W1);
    spmm_relu<true><<<WGRID, 256>>>(b1, p1);
    pool_apply<<<Bz * 4, 256>>>(1);

    // layer 2
    gemm_fused<Ff, true, true><<<WGRID, 256>>>(nullptr, W2);
    spmm_relu<false><<<WGRID, 256>>>(b2, nullptr);

    final_fc<<<Bz, 512>>>(Wfc, bfc, out);
}

// round 4
// speedup vs baseline: 1.3105x; 1.0268x over previous
#include <cuda_runtime.h>
#include <math.h>

#define Bz   32
#define Nn   1024
#define CIN  128
#define Ff   64
#define OUTD 10
#define MAXDEG 192
#define EPSf 1e-5f

// ---------------- scratch (device globals; no allocation) ----------------
__device__ int   g_adj[Bz * Nn * MAXDEG];   // adjacency lists (compacted per layer)
__device__ int   g_deg[Bz * Nn];
__device__ float g_x[Bz * Nn * Ff];         // gconv output
__device__ float g_uw[Bz * Nn * Ff];        // D*m*u  (gathered by spmm)
__device__ float g_ud[Bz * Nn * Ff];        // D*D*u  (diag term)
__device__ float g_D[Bz * Nn];
__device__ float g_mask[Bz * Nn];
__device__ float g_sc[Bz * Nn];             // tanh(y)*new_mask (folded into next gemm)
__device__ int   g_nnodes[Bz * 3];
__device__ float g_y[Bz * Nn];

// ---------------- 1) adjacency extraction: one pass over A ----------------
__global__ void build_adj(const float* __restrict__ A,
                          const float* __restrict__ mask,
                          const int*   __restrict__ nn) {
    int warp = (blockIdx.x * blockDim.x + threadIdx.x) >> 5;
    int lane = threadIdx.x & 31;
    if (blockIdx.x == 0 && threadIdx.x < Bz) g_nnodes[threadIdx.x] = nn[threadIdx.x];
    if (warp >= Bz * Nn) return;
    const float* row = A + (size_t)warp * Nn;
    int* out = g_adj + (size_t)warp * MAXDEG;
    int cnt = 0;
    #pragma unroll 4
    for (int it = 0; it < Nn / 32; ++it) {
        int j = it * 32 + lane;
        float v = row[j];
        unsigned bal = __ballot_sync(0xffffffffu, v != 0.0f);
        if (v != 0.0f) {
            int pos = cnt + __popc(bal & ((1u << lane) - 1u));
            if (pos < MAXDEG) out[pos] = j;
        }
        cnt += __popc(bal);
    }
    if (lane == 0) {
        g_deg[warp]  = min(cnt, MAXDEG);
        g_mask[warp] = mask[warp];
    }
}

// ------- 2) fused: u = sc*(X@W); D/degree; adj compaction; uw/ud ---------
template <int K, bool FROMG, bool SC>
__global__ void gemm_fused(const float* __restrict__ Xext,
                           const float* __restrict__ W) {
    __shared__ float2 Ws[K * 32];
    __shared__ float  Xs[8][K];
    const float* X = FROMG ? (const float*)g_x : Xext;
    const float2* W2 = (const float2*)W;
    for (int i = threadIdx.x; i < K * 32; i += blockDim.x) Ws[i] = W2[i];
    int wid = threadIdx.x >> 5, lane = threadIdx.x & 31;
    int row = blockIdx.x * 8 + wid;
    __syncthreads();
    const float* xr = X + (size_t)row * K;
    #pragma unroll
    for (int k = lane; k < K; k += 32) Xs[wid][k] = xr[k];
    __syncwarp();
    float a0 = 0.f, a1 = 0.f;
    #pragma unroll 8
    for (int k = 0; k < K; ++k) {
        float xv = Xs[wid][k];
        float2 wv = Ws[k * 32 + lane];
        a0 = fmaf(xv, wv.x, a0);
        a1 = fmaf(xv, wv.y, a1);
    }
    if (SC) {                                 // pooling rescale: (sc*x)@W == sc*(x@W)
        float s = g_sc[row];
        a0 *= s; a1 *= s;
    }
    // --- fused degree count + in-place adjacency compaction under mask ---
    int base = row & ~(Nn - 1);
    float m  = g_mask[row];
    int  deg = g_deg[row];
    int* adj = g_adj + (size_t)row * MAXDEG;
    int wcnt = 0;
    for (int c = 0; c < deg; c += 32) {
        int idx = c + lane;
        int j = (idx < deg) ? adj[idx] : 0;
        bool act = (idx < deg) && (g_mask[base + j] > 0.f);
        unsigned bal = __ballot_sync(0xffffffffu, act);
        if (act) adj[wcnt + __popc(bal & ((1u << lane) - 1u))] = j;
        wcnt += __popc(bal);
    }
    float rowsum = m * (float)wcnt + 1.0f;    // +1: identity in A_hat
    float D = 1.0f / sqrtf(rowsum + EPSf);
    if (lane == 0) { g_deg[row] = wcnt; g_D[row] = D; }
    float Dm = D * m, DD = D * D;
    ((float2*)g_uw)[(size_t)row * 32 + lane] = make_float2(Dm * a0, Dm * a1);
    ((float2*)g_ud)[(size_t)row * 32 + lane] = make_float2(DD * a0, DD * a1);
}

// -------- 3) x = relu(D*sum_adj(uw_j) + ud_i + b)  [+ pooling score] ------
template <bool POOL>
__global__ void spmm_relu(const float* __restrict__ bias,
                          const float* __restrict__ p) {
    int node = (blockIdx.x * blockDim.x + threadIdx.x) >> 5;
    int lane = threadIdx.x & 31;
    if (node >= Bz * Nn) return;
    int base = node & ~(Nn - 1);
    float D = g_D[node];
    float2 ud = ((const float2*)g_ud)[(size_t)node * 32 + lane];
    float2 bv = ((const float2*)bias)[lane];
    float s0 = 0.f, s1 = 0.f;
    if (g_mask[node] > 0.f) {
        const int* adj = g_adj + (size_t)node * MAXDEG;
        int deg = g_deg[node];
        const float2* uwb = (const float2*)g_uw + (size_t)base * 32 + lane;
        int t = 0;
        for (; t + 4 <= deg; t += 4) {
            int4 jv = *(const int4*)(adj + t);
            float2 v0 = uwb[jv.x * 32];
            float2 v1 = uwb[jv.y * 32];
            float2 v2 = uwb[jv.z * 32];
            float2 v3 = uwb[jv.w * 32];
            s0 += (v0.x + v1.x) + (v2.x + v3.x);
            s1 += (v0.y + v1.y) + (v2.y + v3.y);
        }
        for (; t < deg; ++t) {
            float2 v = uwb[adj[t] * 32];
            s0 += v.x; s1 += v.y;
        }
    }
    float x0 = fmaxf(fmaf(D, s0, ud.x + bv.x), 0.f);
    float x1 = fmaxf(fmaf(D, s1, ud.y + bv.y), 0.f);
    ((float2*)g_x)[(size_t)node * 32 + lane] = make_float2(x0, x1);
    if (POOL) {
        float2 pv = ((const float2*)p)[lane];
        float d = x0 * pv.x + x1 * pv.y;
        float n = pv.x * pv.x + pv.y * pv.y;
        #pragma unroll
        for (int o = 16; o; o >>= 1) {
            d += __shfl_xor_sync(0xffffffffu, d, o);
            n += __shfl_xor_sync(0xffffffffu, n, o);
        }
        if (lane == 0) g_y[node] = d / sqrtf(n);
    }
}

// -------- 4) ranks + drop -> sc, mask (8 blocks/graph, float4 + 4-acc) ----
__global__ void pool_apply(int step) {
    __shared__ float4 ys4[Nn / 4];
    float* ys = (float*)ys4;
    int b = blockIdx.x >> 3;                  // 8 blocks per graph
    int i = (blockIdx.x & 7) * 128 + threadIdx.x;
    int node = b * Nn + i;
    for (int j = threadIdx.x; j < Nn; j += 128) {
        float mj = g_mask[b * Nn + j];
        ys[j] = (mj > 0.f) ? g_y[b * Nn + j] : INFINITY;
    }
    if ((blockIdx.x & 7) == 0 && threadIdx.x == 0) {
        int n  = g_nnodes[step * Bz + b];
        int nr = (int)((float)n * 0.2f);      // bit-matches f32 arithmetic
        g_nnodes[(step + 1) * Bz + b] = n - nr;
    }
    __syncthreads();
    float m  = g_mask[node];
    float y  = g_y[node];
    float ye = ys[i];
    int r0 = 0, r1 = 0, r2 = 0, r3 = 0;       // 4 independent chains
    #pragma unroll 4
    for (int q = 0; q < Nn / 4; ++q) {
        float4 v = ys4[q];
        int j = q * 4;
        r0 += (v.x < ye) || ((v.x == ye) && (j     < i));
        r1 += (v.y < ye) || ((v.y == ye) && (j + 1 < i));
        r2 += (v.z < ye) || ((v.z == ye) && (j + 2 < i));
        r3 += (v.w < ye) || ((v.w == ye) && (j + 3 < i));
    }
    int rank = (r0 + r1) + (r2 + r3);         // stable argsort rank
    int n  = g_nnodes[step * Bz + b];
    int nr = (int)((float)n * 0.2f);
    float newm = (m > 0.f && rank >= nr) ? 1.f : 0.f;
    g_mask[node] = newm;
    g_sc[node]   = tanhf(y) * newm;
}

// ---------------- 5) global max over nodes + final FC ---------------------
__global__ void final_fc(const float* __restrict__ Wfc,
                         const float* __restrict__ bfc,
                         float* __restrict__ out) {
    __shared__ float pm[8][Ff];
    __shared__ float gm[Ff];
    int b = blockIdx.x;
    int f = threadIdx.x & 63;
    int c = threadIdx.x >> 6;
    const float* xb = g_x + (size_t)b * Nn * Ff;
    float mx = -INFINITY;
    for (int node = c; node < Nn; node += 8)
        mx = fmaxf(mx, xb[node * Ff + f]);
    pm[c][f] = mx;
    __syncthreads();
    if (threadIdx.x < Ff) {
        float v = pm[0][f];
        #pragma unroll
        for (int k = 1; k < 8; ++k) v = fmaxf(v, pm[k][f]);
        gm[f] = v;
    }
    __syncthreads();
    if (threadIdx.x < OUTD) {
        float acc = bfc[threadIdx.x];
        #pragma unroll
        for (int ff = 0; ff < Ff; ++ff)
            acc = fmaf(gm[ff], Wfc[ff * OUTD + threadIdx.x], acc);
        out[b * OUTD + threadIdx.x] = acc;
    }
}

// ---------------- launch ---------------------------------------------------
extern "C" void kernel_launch(void* const* d_in, const int* in_sizes, int n_in,
                              void* d_out, int out_size) {
    const float* x    = (const float*)d_in[0];
    const float* A    = (const float*)d_in[1];
    const float* mask = (const float*)d_in[2];
    const int*   nn   = (const int*)  d_in[3];
    const float* W0   = (const float*)d_in[4];
    const float* b0   = (const float*)d_in[5];
    const float* W1   = (const float*)d_in[6];
    const float* b1   = (const float*)d_in[7];
    const float* W2   = (const float*)d_in[8];
    const float* b2   = (const float*)d_in[9];
    const float* p0   = (const float*)d_in[10];
    const float* p1   = (const float*)d_in[11];
    const float* Wfc  = (const float*)d_in[12];
    const float* bfc  = (const float*)d_in[13];
    float* out = (float*)d_out;

    const int WGRID = (Bz * Nn) / 8;   // 8 warps per 256-thread block

    build_adj<<<WGRID, 256>>>(A, mask, nn);

    // layer 0
    gemm_fused<CIN, false, false><<<WGRID, 256>>>(x, W0);
    spmm_relu<true><<<WGRID, 256>>>(b0, p0);
    pool_apply<<<Bz * 8, 128>>>(0);

    // layer 1
    gemm_fused<Ff, true, true><<<WGRID, 256>>>(nullptr, W1);
    spmm_relu<true><<<WGRID, 256>>>(b1, p1);
    pool_apply<<<Bz * 8, 128>>>(1);

    // layer 2
    gemm_fused<Ff, true, true><<<WGRID, 256>>>(nullptr, W2);
    spmm_relu<false><<<WGRID, 256>>>(b2, nullptr);

    final_fc<<<Bz, 512>>>(Wfc, bfc, out);
}

// round 5
// speedup vs baseline: 1.3805x; 1.0535x over previous
#include <cuda_runtime.h>
#include <math.h>

#define Bz   32
#define Nn   1024
#define CIN  128
#define Ff   64
#define OUTD 10
#define MAXDEG 192
#define EPSf 1e-5f

// ---------------- scratch (device globals; no allocation) ----------------
__device__ int   g_adj[Bz * Nn * MAXDEG];   // adjacency lists (compacted per layer)
__device__ int   g_deg[Bz * Nn];
__device__ float g_x[Bz * Nn * Ff];         // gconv output
__device__ float g_uw[Bz * Nn * Ff];        // D*m*u  (gathered by spmm)
__device__ float g_ud[Bz * Nn * Ff];        // D*D*u  (diag term)
__device__ float g_D[Bz * Nn];
__device__ float g_mask[Bz * Nn];
__device__ float g_sc[Bz * Nn];             // tanh(y)*new_mask (folded into next gemm)
__device__ int   g_nnodes[Bz * 3];
__device__ float g_y[Bz * Nn];

// ---------------- 1) adjacency extraction: one pass over A ----------------
__global__ void build_adj(const float* __restrict__ A,
                          const float* __restrict__ mask,
                          const int*   __restrict__ nn) {
    int warp = (blockIdx.x * blockDim.x + threadIdx.x) >> 5;
    int lane = threadIdx.x & 31;
    if (blockIdx.x == 0 && threadIdx.x < Bz) g_nnodes[threadIdx.x] = nn[threadIdx.x];
    if (warp >= Bz * Nn) return;
    const float* row = A + (size_t)warp * Nn;
    int* out = g_adj + (size_t)warp * MAXDEG;
    int cnt = 0;
    #pragma unroll 4
    for (int it = 0; it < Nn / 32; ++it) {
        int j = it * 32 + lane;
        float v = row[j];
        unsigned bal = __ballot_sync(0xffffffffu, v != 0.0f);
        if (v != 0.0f) {
            int pos = cnt + __popc(bal & ((1u << lane) - 1u));
            if (pos < MAXDEG) out[pos] = j;
        }
        cnt += __popc(bal);
    }
    if (lane == 0) {
        g_deg[warp]  = min(cnt, MAXDEG);
        g_mask[warp] = mask[warp];
    }
}

// ------- 2) fused: u = sc*(X@W); D/degree; adj compaction; uw/ud ---------
template <int K, bool FROMG, bool SC>
__global__ void gemm_fused(const float* __restrict__ Xext,
                           const float* __restrict__ W) {
    __shared__ float2 Ws[K * 32];
    __shared__ float  Xs[8][K];
    const float* X = FROMG ? (const float*)g_x : Xext;
    const float2* W2 = (const float2*)W;
    for (int i = threadIdx.x; i < K * 32; i += blockDim.x) Ws[i] = W2[i];
    int wid = threadIdx.x >> 5, lane = threadIdx.x & 31;
    int row = blockIdx.x * 8 + wid;
    __syncthreads();
    const float* xr = X + (size_t)row * K;
    #pragma unroll
    for (int k = lane; k < K; k += 32) Xs[wid][k] = xr[k];
    __syncwarp();
    float a0 = 0.f, a1 = 0.f;
    #pragma unroll 8
    for (int k = 0; k < K; ++k) {
        float xv = Xs[wid][k];
        float2 wv = Ws[k * 32 + lane];
        a0 = fmaf(xv, wv.x, a0);
        a1 = fmaf(xv, wv.y, a1);
    }
    if (SC) {                                 // pooling rescale: (sc*x)@W == sc*(x@W)
        float s = g_sc[row];
        a0 *= s; a1 *= s;
    }
    // --- fused degree count + in-place adjacency compaction under mask ---
    int base = row & ~(Nn - 1);
    float m  = g_mask[row];
    int  deg = g_deg[row];
    int* adj = g_adj + (size_t)row * MAXDEG;
    int wcnt = 0;
    for (int c = 0; c < deg; c += 32) {
        int idx = c + lane;
        int j = (idx < deg) ? adj[idx] : 0;
        bool act = (idx < deg) && (g_mask[base + j] > 0.f);
        unsigned bal = __ballot_sync(0xffffffffu, act);
        if (act) adj[wcnt + __popc(bal & ((1u << lane) - 1u))] = j;
        wcnt += __popc(bal);
    }
    float rowsum = m * (float)wcnt + 1.0f;    // +1: identity in A_hat
    float D = 1.0f / sqrtf(rowsum + EPSf);
    if (lane == 0) { g_deg[row] = wcnt; g_D[row] = D; }
    float Dm = D * m, DD = D * D;
    ((float2*)g_uw)[(size_t)row * 32 + lane] = make_float2(Dm * a0, Dm * a1);
    ((float2*)g_ud)[(size_t)row * 32 + lane] = make_float2(DD * a0, DD * a1);
}

// -------- 3) x = relu(D*sum_adj(uw_j) + ud_i + b)  [+ pooling score] ------
template <bool POOL>
__global__ void spmm_relu(const float* __restrict__ bias,
                          const float* __restrict__ p) {
    int node = (blockIdx.x * blockDim.x + threadIdx.x) >> 5;
    int lane = threadIdx.x & 31;
    if (node >= Bz * Nn) return;
    int base = node & ~(Nn - 1);
    float D = g_D[node];
    float2 ud = ((const float2*)g_ud)[(size_t)node * 32 + lane];
    float2 bv = ((const float2*)bias)[lane];
    float s0 = 0.f, s1 = 0.f;
    if (g_mask[node] > 0.f) {
        const int* adj = g_adj + (size_t)node * MAXDEG;
        int deg = g_deg[node];
        const float2* uwb = (const float2*)g_uw + (size_t)base * 32 + lane;
        int t = 0;
        for (; t + 4 <= deg; t += 4) {
            int4 jv = *(const int4*)(adj + t);
            float2 v0 = uwb[jv.x * 32];
            float2 v1 = uwb[jv.y * 32];
            float2 v2 = uwb[jv.z * 32];
            float2 v3 = uwb[jv.w * 32];
            s0 += (v0.x + v1.x) + (v2.x + v3.x);
            s1 += (v0.y + v1.y) + (v2.y + v3.y);
        }
        for (; t < deg; ++t) {
            float2 v = uwb[adj[t] * 32];
            s0 += v.x; s1 += v.y;
        }
    }
    float x0 = fmaxf(fmaf(D, s0, ud.x + bv.x), 0.f);
    float x1 = fmaxf(fmaf(D, s1, ud.y + bv.y), 0.f);
    ((float2*)g_x)[(size_t)node * 32 + lane] = make_float2(x0, x1);
    if (POOL) {
        float2 pv = ((const float2*)p)[lane];
        float d = x0 * pv.x + x1 * pv.y;
        float n = pv.x * pv.x + pv.y * pv.y;
        #pragma unroll
        for (int o = 16; o; o >>= 1) {
            d += __shfl_xor_sync(0xffffffffu, d, o);
            n += __shfl_xor_sync(0xffffffffu, n, o);
        }
        if (lane == 0) g_y[node] = d / sqrtf(n);
    }
}

// -------- 4) pooling via bitonic sort of 64-bit (value,index) keys --------
// one block of 1024 threads per graph; stable rank == sorted position
__global__ void pool_apply(int step) {
    __shared__ unsigned long long keys[Nn];
    __shared__ unsigned char     rem[Nn];
    int b = blockIdx.x;
    int i = threadIdx.x;
    int node = b * Nn + i;
    float m = g_mask[node];
    float y = g_y[node];
    float ye = (m > 0.f) ? y : INFINITY;      // invalid nodes sort last
    unsigned int bits = __float_as_uint(ye);
    unsigned int mono = (bits & 0x80000000u) ? ~bits : (bits | 0x80000000u);
    keys[i] = ((unsigned long long)mono << 10) | (unsigned int)i;
    rem[i] = 0;
    int n  = g_nnodes[step * Bz + b];
    int nr = (int)((float)n * 0.2f);          // bit-matches f32 arithmetic
    if (i == 0) g_nnodes[(step + 1) * Bz + b] = n - nr;
    __syncthreads();
    #pragma unroll 1
    for (int k = 2; k <= Nn; k <<= 1) {
        #pragma unroll 1
        for (int j = k >> 1; j > 0; j >>= 1) {
            int ixj = i ^ j;
            if (ixj > i) {
                unsigned long long a = keys[i], c = keys[ixj];
                bool up = ((i & k) == 0);
                if ((a > c) == up) { keys[i] = c; keys[ixj] = a; }
            }
            __syncthreads();
        }
    }
    if (i < nr) rem[(int)(keys[i] & 1023u)] = 1;   // lowest-nr ranks removed
    __syncthreads();
    float newm = (m > 0.f && !rem[i]) ? 1.f : 0.f;
    g_mask[node] = newm;
    g_sc[node]   = tanhf(y) * newm;               // consumed by next gemm
}

// ---------------- 5) global max over nodes + final FC ---------------------
__global__ void final_fc(const float* __restrict__ Wfc,
                         const float* __restrict__ bfc,
                         float* __restrict__ out) {
    __shared__ float pm[8][Ff];
    __shared__ float gm[Ff];
    int b = blockIdx.x;
    int f = threadIdx.x & 63;
    int c = threadIdx.x >> 6;
    const float* xb = g_x + (size_t)b * Nn * Ff;
    float mx = -INFINITY;
    for (int node = c; node < Nn; node += 8)
        mx = fmaxf(mx, xb[node * Ff + f]);
    pm[c][f] = mx;
    __syncthreads();
    if (threadIdx.x < Ff) {
        float v = pm[0][f];
        #pragma unroll
        for (int k = 1; k < 8; ++k) v = fmaxf(v, pm[k][f]);
        gm[f] = v;
    }
    __syncthreads();
    if (threadIdx.x < OUTD) {
        float acc = bfc[threadIdx.x];
        #pragma unroll
        for (int ff = 0; ff < Ff; ++ff)
            acc = fmaf(gm[ff], Wfc[ff * OUTD + threadIdx.x], acc);
        out[b * OUTD + threadIdx.x] = acc;
    }
}

// ---------------- launch ---------------------------------------------------
extern "C" void kernel_launch(void* const* d_in, const int* in_sizes, int n_in,
                              void* d_out, int out_size) {
    const float* x    = (const float*)d_in[0];
    const float* A    = (const float*)d_in[1];
    const float* mask = (const float*)d_in[2];
    const int*   nn   = (const int*)  d_in[3];
    const float* W0   = (const float*)d_in[4];
    const float* b0   = (const float*)d_in[5];
    const float* W1   = (const float*)d_in[6];
    const float* b1   = (const float*)d_in[7];
    const float* W2   = (const float*)d_in[8];
    const float* b2   = (const float*)d_in[9];
    const float* p0   = (const float*)d_in[10];
    const float* p1   = (const float*)d_in[11];
    const float* Wfc  = (const float*)d_in[12];
    const float* bfc  = (const float*)d_in[13];
    float* out = (float*)d_out;

    const int WGRID = (Bz * Nn) / 8;   // 8 warps per 256-thread block

    build_adj<<<WGRID, 256>>>(A, mask, nn);

    // layer 0
    gemm_fused<CIN, false, false><<<WGRID, 256>>>(x, W0);
    spmm_relu<true><<<WGRID, 256>>>(b0, p0);
    pool_apply<<<Bz, Nn>>>(0);

    // layer 1
    gemm_fused<Ff, true, true><<<WGRID, 256>>>(nullptr, W1);
    spmm_relu<true><<<WGRID, 256>>>(b1, p1);
    pool_apply<<<Bz, Nn>>>(1);

    // layer 2
    gemm_fused<Ff, true, true><<<WGRID, 256>>>(nullptr, W2);
    spmm_relu<false><<<WGRID, 256>>>(b2, nullptr);

    final_fc<<<Bz, 512>>>(Wfc, bfc, out);
}

// round 6
// speedup vs baseline: 1.4205x; 1.0289x over previous
#include <cuda_runtime.h>
#include <math.h>

#define Bz   32
#define Nn   1024
#define CIN  128
#define Ff   64
#define OUTD 10
#define MAXDEG 192
#define EPSf 1e-5f

typedef unsigned long long ull;

// ---------------- scratch (device globals; no allocation) ----------------
__device__ int   g_adj[Bz * Nn * MAXDEG];   // adjacency lists (compacted per layer)
__device__ int   g_deg[Bz * Nn];
__device__ float g_x[Bz * Nn * Ff];         // gconv output (layers 0,1)
__device__ float g_uw[Bz * Nn * Ff];        // D*m*u  (gathered by spmm)
__device__ float g_ud[Bz * Nn * Ff];        // D*D*u  (diag term)
__device__ float g_D[Bz * Nn];
__device__ float g_mask[Bz * Nn];
__device__ float g_sc[Bz * Nn];             // tanh(y)*new_mask (folded into next gemm)
__device__ int   g_nnodes[Bz * 3];
__device__ float g_y[Bz * Nn];
__device__ float g_xmax[Bz * Ff];           // layer-2 global max (atomicMax target)

// ------ 1) fused: adjacency extraction + layer-0 GEMM + D + uw/ud --------
// A is pre-masked (A*m_i*m_j) so layer-0 compaction is a no-op: wcnt == deg.
__global__ void layer0_fused(const float* __restrict__ x,
                             const float* __restrict__ A,
                             const float* __restrict__ mask,
                             const int*   __restrict__ nn,
                             const float* __restrict__ W) {
    __shared__ float2 Ws[CIN * 32];
    __shared__ float  Xs[8][CIN];
    const float2* W2 = (const float2*)W;
    for (int i = threadIdx.x; i < CIN * 32; i += 256) Ws[i] = W2[i];
    if (blockIdx.x == 0 && threadIdx.x < Bz) g_nnodes[threadIdx.x] = nn[threadIdx.x];
    int wid = threadIdx.x >> 5, lane = threadIdx.x & 31;
    int row = blockIdx.x * 8 + wid;
    const float* xr = x + (size_t)row * CIN;
    #pragma unroll
    for (int k = lane; k < CIN; k += 32) Xs[wid][k] = xr[k];
    // --- adjacency scan of A row (DRAM-bound; GEMM hides under it) ---
    const float* Arow = A + (size_t)row * Nn;
    int* adj = g_adj + (size_t)row * MAXDEG;
    int cnt = 0;
    #pragma unroll 4
    for (int it = 0; it < Nn / 32; ++it) {
        int j = it * 32 + lane;
        float v = Arow[j];
        unsigned bal = __ballot_sync(0xffffffffu, v != 0.0f);
        if (v != 0.0f) {
            int pos = cnt + __popc(bal & ((1u << lane) - 1u));
            if (pos < MAXDEG) adj[pos] = j;
        }
        cnt += __popc(bal);
    }
    int deg = min(cnt, MAXDEG);
    float m = mask[row];
    if (lane == 0) { g_deg[row] = deg; g_mask[row] = m; }
    __syncthreads();
    // --- GEMM u = x @ W0 ---
    float a0 = 0.f, a1 = 0.f;
    #pragma unroll 8
    for (int k = 0; k < CIN; ++k) {
        float xv = Xs[wid][k];
        float2 wv = Ws[k * 32 + lane];
        a0 = fmaf(xv, wv.x, a0);
        a1 = fmaf(xv, wv.y, a1);
    }
    float rowsum = m * (float)deg + 1.0f;     // +1: identity in A_hat
    float D = 1.0f / sqrtf(rowsum + EPSf);
    if (lane == 0) g_D[row] = D;
    float Dm = D * m, DD = D * D;
    ((float2*)g_uw)[(size_t)row * 32 + lane] = make_float2(Dm * a0, Dm * a1);
    ((float2*)g_ud)[(size_t)row * 32 + lane] = make_float2(DD * a0, DD * a1);
}

// ------- 2) fused: u = sc*(X@W); D/degree; adj compaction; uw/ud ---------
template <int K>
__global__ void gemm_fused(const float* __restrict__ W) {
    __shared__ float2 Ws[K * 32];
    __shared__ float  Xs[8][K];
    const float2* W2 = (const float2*)W;
    for (int i = threadIdx.x; i < K * 32; i += blockDim.x) Ws[i] = W2[i];
    int wid = threadIdx.x >> 5, lane = threadIdx.x & 31;
    int row = blockIdx.x * 8 + wid;
    __syncthreads();
    const float* xr = g_x + (size_t)row * K;
    #pragma unroll
    for (int k = lane; k < K; k += 32) Xs[wid][k] = xr[k];
    __syncwarp();
    float a0 = 0.f, a1 = 0.f;
    #pragma unroll 8
    for (int k = 0; k < K; ++k) {
        float xv = Xs[wid][k];
        float2 wv = Ws[k * 32 + lane];
        a0 = fmaf(xv, wv.x, a0);
        a1 = fmaf(xv, wv.y, a1);
    }
    float s = g_sc[row];                      // pooling rescale: (sc*x)@W == sc*(x@W)
    a0 *= s; a1 *= s;
    // --- fused degree count + in-place adjacency compaction under mask ---
    int base = row & ~(Nn - 1);
    float m  = g_mask[row];
    int  deg = g_deg[row];
    int* adj = g_adj + (size_t)row * MAXDEG;
    int wcnt = 0;
    for (int c = 0; c < deg; c += 32) {
        int idx = c + lane;
        int j = (idx < deg) ? adj[idx] : 0;
        bool act = (idx < deg) && (g_mask[base + j] > 0.f);
        unsigned bal = __ballot_sync(0xffffffffu, act);
        if (act) adj[wcnt + __popc(bal & ((1u << lane) - 1u))] = j;
        wcnt += __popc(bal);
    }
    float rowsum = m * (float)wcnt + 1.0f;
    float D = 1.0f / sqrtf(rowsum + EPSf);
    if (lane == 0) { g_deg[row] = wcnt; g_D[row] = D; }
    float Dm = D * m, DD = D * D;
    ((float2*)g_uw)[(size_t)row * 32 + lane] = make_float2(Dm * a0, Dm * a1);
    ((float2*)g_ud)[(size_t)row * 32 + lane] = make_float2(DD * a0, DD * a1);
}

// -------------- shared gather body for spmm variants ----------------------
__device__ __forceinline__ float2 spmm_body(int node, int lane,
                                            const float* __restrict__ bias) {
    int base = node & ~(Nn - 1);
    float D = g_D[node];
    float2 ud = ((const float2*)g_ud)[(size_t)node * 32 + lane];
    float2 bv = ((const float2*)bias)[lane];
    float s0 = 0.f, s1 = 0.f;
    if (g_mask[node] > 0.f) {
        const int* adj = g_adj + (size_t)node * MAXDEG;
        int deg = g_deg[node];
        const float2* uwb = (const float2*)g_uw + (size_t)base * 32 + lane;
        int t = 0;
        for (; t + 4 <= deg; t += 4) {
            int4 jv = *(const int4*)(adj + t);
            float2 v0 = uwb[jv.x * 32];
            float2 v1 = uwb[jv.y * 32];
            float2 v2 = uwb[jv.z * 32];
            float2 v3 = uwb[jv.w * 32];
            s0 += (v0.x + v1.x) + (v2.x + v3.x);
            s1 += (v0.y + v1.y) + (v2.y + v3.y);
        }
        for (; t < deg; ++t) {
            float2 v = uwb[adj[t] * 32];
            s0 += v.x; s1 += v.y;
        }
    }
    float x0 = fmaxf(fmaf(D, s0, ud.x + bv.x), 0.f);
    float x1 = fmaxf(fmaf(D, s1, ud.y + bv.y), 0.f);
    return make_float2(x0, x1);
}

// -------- 3) layers 0/1: x = gconv, + fused pooling score -----------------
__global__ void spmm_relu(const float* __restrict__ bias,
                          const float* __restrict__ p) {
    int node = (blockIdx.x * blockDim.x + threadIdx.x) >> 5;
    int lane = threadIdx.x & 31;
    float2 xv = spmm_body(node, lane, bias);
    ((float2*)g_x)[(size_t)node * 32 + lane] = xv;
    float2 pv = ((const float2*)p)[lane];
    float d = xv.x * pv.x + xv.y * pv.y;
    float n = pv.x * pv.x + pv.y * pv.y;
    #pragma unroll
    for (int o = 16; o; o >>= 1) {
        d += __shfl_xor_sync(0xffffffffu, d, o);
        n += __shfl_xor_sync(0xffffffffu, n, o);
    }
    if (lane == 0) g_y[node] = d / sqrtf(n);
}

// -------- 3b) layer 2: gconv fused with global max (no g_x write) ---------
__global__ void spmm_max(const float* __restrict__ bias) {
    __shared__ float2 pm[8][32];
    int node = (blockIdx.x * blockDim.x + threadIdx.x) >> 5;
    int wid  = threadIdx.x >> 5;
    int lane = threadIdx.x & 31;
    float2 xv = spmm_body(node, lane, bias);
    pm[wid][lane] = xv;
    __syncthreads();
    if (wid == 0) {
        float2 mx = pm[0][lane];
        #pragma unroll
        for (int w = 1; w < 8; ++w) {
            float2 v = pm[w][lane];
            mx.x = fmaxf(mx.x, v.x);
            mx.y = fmaxf(mx.y, v.y);
        }
        int b = node >> 10;
        unsigned* gx = (unsigned*)g_xmax + b * Ff + 2 * lane;
        atomicMax(gx,     __float_as_uint(mx.x));   // x >= 0: bits monotone
        atomicMax(gx + 1, __float_as_uint(mx.y));
    }
}

// -------- 4) pooling via hybrid register/shared bitonic sort --------------
// one block of 1024 threads per graph; key = (monotone(y_eff)<<10)|idx
__device__ __forceinline__ ull bsw(ull v, int i, int j, int k) {
    ull vp = __shfl_xor_sync(0xffffffffu, v, j);
    bool keepmin = ((i & j) == 0) == ((i & k) == 0);
    ull mn = v < vp ? v : vp;
    ull mx = v < vp ? vp : v;
    return keepmin ? mn : mx;
}

__global__ void pool_apply(int step) {
    __shared__ ull sk[Nn];
    __shared__ unsigned char rem[Nn];
    int b = blockIdx.x;
    int i = threadIdx.x;
    int node = b * Nn + i;
    float m = g_mask[node];
    float y = g_y[node];
    float ye = (m > 0.f) ? y : INFINITY;      // invalid nodes sort last
    unsigned int bits = __float_as_uint(ye);
    unsigned int mono = (bits & 0x80000000u) ? ~bits : (bits | 0x80000000u);
    ull v = ((ull)mono << 10) | (unsigned int)i;
    rem[i] = 0;
    if (step == 1 && i < Ff) g_xmax[b * Ff + i] = 0.f;   // reset for spmm_max
    int n  = g_nnodes[step * Bz + b];
    int nr = (int)((float)n * 0.2f);          // bit-matches f32 arithmetic
    if (i == 0) g_nnodes[(step + 1) * Bz + b] = n - nr;
    // in-warp stages k = 2..32 (no barriers)
    #pragma unroll
    for (int k = 2; k <= 32; k <<= 1)
        #pragma unroll
        for (int j = k >> 1; j > 0; j >>= 1) v = bsw(v, i, j, k);
    // stages k = 64..1024: shared exchange while j>=32, then in-warp
    #pragma unroll 1
    for (int k = 64; k <= Nn; k <<= 1) {
        #pragma unroll 1
        for (int j = k >> 1; j >= 32; j >>= 1) {
            sk[i] = v;
            __syncthreads();
            ull vp = sk[i ^ j];
            bool keepmin = ((i & j) == 0) == ((i & k) == 0);
            v = keepmin ? (v < vp ? v : vp) : (v < vp ? vp : v);
            __syncthreads();
        }
        #pragma unroll
        for (int j = 16; j > 0; j >>= 1) v = bsw(v, i, j, k);
    }
    if (i < nr) rem[(int)(v & 1023u)] = 1;    // lowest-nr ranks removed
    __syncthreads();
    float newm = (m > 0.f && !rem[i]) ? 1.f : 0.f;
    g_mask[node] = newm;
    g_sc[node]   = tanhf(y) * newm;           // consumed by next gemm
}

// ---------------- 5) tiny final FC from g_xmax ----------------------------
__global__ void final_fc(const float* __restrict__ Wfc,
                         const float* __restrict__ bfc,
                         float* __restrict__ out) {
    __shared__ float gm[Ff];
    int b = blockIdx.x;
    if (threadIdx.x < Ff) gm[threadIdx.x] = g_xmax[b * Ff + threadIdx.x];
    __syncthreads();
    if (threadIdx.x < OUTD) {
        float acc = bfc[threadIdx.x];
        #pragma unroll
        for (int ff = 0; ff < Ff; ++ff)
            acc = fmaf(gm[ff], Wfc[ff * OUTD + threadIdx.x], acc);
        out[b * OUTD + threadIdx.x] = acc;
    }
}

// ---------------- launch ---------------------------------------------------
extern "C" void kernel_launch(void* const* d_in, const int* in_sizes, int n_in,
                              void* d_out, int out_size) {
    const float* x    = (const float*)d_in[0];
    const float* A    = (const float*)d_in[1];
    const float* mask = (const float*)d_in[2];
    const int*   nn   = (const int*)  d_in[3];
    const float* W0   = (const float*)d_in[4];
    const float* b0   = (const float*)d_in[5];
    const float* W1   = (const float*)d_in[6];
    const float* b1   = (const float*)d_in[7];
    const float* W2   = (const float*)d_in[8];
    const float* b2   = (const float*)d_in[9];
    const float* p0   = (const float*)d_in[10];
    const float* p1   = (const float*)d_in[11];
    const float* Wfc  = (const float*)d_in[12];
    const float* bfc  = (const float*)d_in[13];
    float* out = (float*)d_out;

    const int WGRID = (Bz * Nn) / 8;   // 8 warps per 256-thread block

    // layer 0 (adjacency build fused with GEMM)
    layer0_fused<<<WGRID, 256>>>(x, A, mask, nn, W0);
    spmm_relu<<<WGRID, 256>>>(b0, p0);
    pool_apply<<<Bz, Nn>>>(0);

    // layer 1
    gemm_fused<Ff><<<WGRID, 256>>>(W1);
    spmm_relu<<<WGRID, 256>>>(b1, p1);
    pool_apply<<<Bz, Nn>>>(1);

    // layer 2 (gconv fused with global max pool)
    gemm_fused<Ff><<<WGRID, 256>>>(W2);
    spmm_max<<<WGRID, 256>>>(b2);

    final_fc<<<Bz, 64>>>(Wfc, bfc, out);
}